// round 1
// baseline (speedup 1.0000x reference)
#include <cuda_runtime.h>

// Problem constants (fixed shapes): B=16, C=512, H=W=64 -> N=4096
#define BATCH 16
#define CH 512
#define NPIX 4096

// Scratch: energy / attention buffer [B, C, C] = 16*512*512 floats = 64MB.
// __device__ global (allocation-free per harness rules).
__device__ float g_energy[(size_t)BATCH * CH * CH];

// ---------------------------------------------------------------------------
// Kernel 1: energy[b,i,j] = sum_n x_low[b,i,n] * x_high[b,j,n]
// Tiled SGEMM: BM=BN=128, BK=16, 256 threads, 8x8 microtile per thread.
// Both operands are K-major (reduction dim contiguous) -> transpose into smem.
// ---------------------------------------------------------------------------
__global__ __launch_bounds__(256, 2) void energy_kernel(
    const float* __restrict__ x_high, const float* __restrict__ x_low)
{
    const int b  = blockIdx.z;
    const int i0 = blockIdx.y * 128;
    const int j0 = blockIdx.x * 128;
    const float* Q = x_low  + (size_t)b * CH * NPIX;  // rows i
    const float* K = x_high + (size_t)b * CH * NPIX;  // rows j

    __shared__ float As[16][132];   // [k][i], +4 pad
    __shared__ float Bs[16][132];   // [k][j]

    const int tid = threadIdx.x;
    const int tx  = tid & 15;       // j-subtile
    const int ty  = tid >> 4;       // i-subtile
    const int k4  = tid & 3;        // load: which float4 along K
    const int lr  = tid >> 2;       // load: row 0..63

    float acc[8][8];
    #pragma unroll
    for (int r = 0; r < 8; r++)
        #pragma unroll
        for (int c = 0; c < 8; c++) acc[r][c] = 0.0f;

    for (int kk = 0; kk < NPIX; kk += 16) {
        #pragma unroll
        for (int s = 0; s < 2; s++) {
            const int row = lr + s * 64;
            float4 va = *(const float4*)(Q + (size_t)(i0 + row) * NPIX + kk + k4 * 4);
            As[k4 * 4 + 0][row] = va.x;
            As[k4 * 4 + 1][row] = va.y;
            As[k4 * 4 + 2][row] = va.z;
            As[k4 * 4 + 3][row] = va.w;
            float4 vb = *(const float4*)(K + (size_t)(j0 + row) * NPIX + kk + k4 * 4);
            Bs[k4 * 4 + 0][row] = vb.x;
            Bs[k4 * 4 + 1][row] = vb.y;
            Bs[k4 * 4 + 2][row] = vb.z;
            Bs[k4 * 4 + 3][row] = vb.w;
        }
        __syncthreads();

        #pragma unroll
        for (int k = 0; k < 16; k++) {
            float af[8], bf[8];
            *(float4*)&af[0] = *(const float4*)&As[k][ty * 8];
            *(float4*)&af[4] = *(const float4*)&As[k][ty * 8 + 4];
            *(float4*)&bf[0] = *(const float4*)&Bs[k][tx * 8];
            *(float4*)&bf[4] = *(const float4*)&Bs[k][tx * 8 + 4];
            #pragma unroll
            for (int r = 0; r < 8; r++)
                #pragma unroll
                for (int c = 0; c < 8; c++)
                    acc[r][c] = fmaf(af[r], bf[c], acc[r][c]);
        }
        __syncthreads();
    }

    float* E = g_energy + ((size_t)b * CH + i0) * CH + j0;
    #pragma unroll
    for (int r = 0; r < 8; r++) {
        float4 c0 = make_float4(acc[r][0], acc[r][1], acc[r][2], acc[r][3]);
        float4 c1 = make_float4(acc[r][4], acc[r][5], acc[r][6], acc[r][7]);
        *(float4*)(E + (size_t)(ty * 8 + r) * CH + tx * 8)     = c0;
        *(float4*)(E + (size_t)(ty * 8 + r) * CH + tx * 8 + 4) = c1;
    }
}

// ---------------------------------------------------------------------------
// Kernel 2: row softmax, in place on g_energy.
// attention = softmax(max_j(e) - e) = softmax(-e) = exp(min(e) - e) / sum.
// One warp per 512-wide row; values live in registers across both passes.
// ---------------------------------------------------------------------------
__global__ __launch_bounds__(256) void softmax_kernel()
{
    const int row  = blockIdx.x * 8 + threadIdx.y;  // 8 warps per block
    const int lane = threadIdx.x;
    float* E = g_energy + (size_t)row * CH;

    float4 v[4];
    #pragma unroll
    for (int k = 0; k < 4; k++)
        v[k] = *(const float4*)(E + lane * 4 + k * 128);

    float mn = v[0].x;
    #pragma unroll
    for (int k = 0; k < 4; k++) {
        mn = fminf(mn, fminf(fminf(v[k].x, v[k].y), fminf(v[k].z, v[k].w)));
    }
    #pragma unroll
    for (int off = 16; off > 0; off >>= 1)
        mn = fminf(mn, __shfl_xor_sync(0xFFFFFFFF, mn, off));

    float sum = 0.0f;
    #pragma unroll
    for (int k = 0; k < 4; k++) {
        v[k].x = __expf(mn - v[k].x);
        v[k].y = __expf(mn - v[k].y);
        v[k].z = __expf(mn - v[k].z);
        v[k].w = __expf(mn - v[k].w);
        sum += v[k].x + v[k].y + v[k].z + v[k].w;
    }
    #pragma unroll
    for (int off = 16; off > 0; off >>= 1)
        sum += __shfl_xor_sync(0xFFFFFFFF, sum, off);

    const float inv = __frcp_rn(sum);
    #pragma unroll
    for (int k = 0; k < 4; k++) {
        v[k].x *= inv; v[k].y *= inv; v[k].z *= inv; v[k].w *= inv;
        *(float4*)(E + lane * 4 + k * 128) = v[k];
    }
}

// ---------------------------------------------------------------------------
// Kernel 3: out[b,i,n] = gamma * sum_j att[b,i,j] * x_high[b,j,n] + x_low[b,i,n]
// Tiled SGEMM: BM=128 (i), BN=128 (n), BK=16 (j). Fused epilogue.
// ---------------------------------------------------------------------------
__global__ __launch_bounds__(256, 2) void out_kernel(
    const float* __restrict__ x_high, const float* __restrict__ x_low,
    const float* __restrict__ gamma, float* __restrict__ out)
{
    const int b  = blockIdx.z;
    const int i0 = blockIdx.y * 128;
    const int n0 = blockIdx.x * 128;
    const float* A = g_energy + (size_t)b * CH * CH;       // attention [i][j]
    const float* K = x_high   + (size_t)b * CH * NPIX;     // [j][n]

    __shared__ float As[16][132];   // [j][i] (transposed)
    __shared__ float Bs[16][128];   // [j][n]

    const int tid = threadIdx.x;
    const int tx  = tid & 15;       // n-subtile
    const int ty  = tid >> 4;       // i-subtile
    const int k4  = tid & 3;
    const int lr  = tid >> 2;       // 0..63
    const int n4  = tid & 31;       // B-tile load: float4 col
    const int br  = tid >> 5;       // B-tile load: row 0..7

    float acc[8][8];
    #pragma unroll
    for (int r = 0; r < 8; r++)
        #pragma unroll
        for (int c = 0; c < 8; c++) acc[r][c] = 0.0f;

    for (int kk = 0; kk < CH; kk += 16) {
        #pragma unroll
        for (int s = 0; s < 2; s++) {
            const int row = lr + s * 64;
            float4 va = *(const float4*)(A + (size_t)(i0 + row) * CH + kk + k4 * 4);
            As[k4 * 4 + 0][row] = va.x;
            As[k4 * 4 + 1][row] = va.y;
            As[k4 * 4 + 2][row] = va.z;
            As[k4 * 4 + 3][row] = va.w;
        }
        #pragma unroll
        for (int s = 0; s < 2; s++) {
            const int jr = br + s * 8;
            *(float4*)&Bs[jr][n4 * 4] =
                *(const float4*)(K + (size_t)(kk + jr) * NPIX + n0 + n4 * 4);
        }
        __syncthreads();

        #pragma unroll
        for (int k = 0; k < 16; k++) {
            float af[8], bf[8];
            *(float4*)&af[0] = *(const float4*)&As[k][ty * 8];
            *(float4*)&af[4] = *(const float4*)&As[k][ty * 8 + 4];
            *(float4*)&bf[0] = *(const float4*)&Bs[k][tx * 8];
            *(float4*)&bf[4] = *(const float4*)&Bs[k][tx * 8 + 4];
            #pragma unroll
            for (int r = 0; r < 8; r++)
                #pragma unroll
                for (int c = 0; c < 8; c++)
                    acc[r][c] = fmaf(af[r], bf[c], acc[r][c]);
        }
        __syncthreads();
    }

    const float g = gamma[0];
    const size_t base = ((size_t)b * CH + i0 + ty * 8) * NPIX + n0 + tx * 8;
    #pragma unroll
    for (int r = 0; r < 8; r++) {
        const size_t off = base + (size_t)r * NPIX;
        float4 xl0 = *(const float4*)(x_low + off);
        float4 xl1 = *(const float4*)(x_low + off + 4);
        float4 o0, o1;
        o0.x = fmaf(g, acc[r][0], xl0.x);
        o0.y = fmaf(g, acc[r][1], xl0.y);
        o0.z = fmaf(g, acc[r][2], xl0.z);
        o0.w = fmaf(g, acc[r][3], xl0.w);
        o1.x = fmaf(g, acc[r][4], xl1.x);
        o1.y = fmaf(g, acc[r][5], xl1.y);
        o1.z = fmaf(g, acc[r][6], xl1.z);
        o1.w = fmaf(g, acc[r][7], xl1.w);
        *(float4*)(out + off)     = o0;
        *(float4*)(out + off + 4) = o1;
    }
}

// ---------------------------------------------------------------------------
extern "C" void kernel_launch(void* const* d_in, const int* in_sizes, int n_in,
                              void* d_out, int out_size)
{
    const float* x_high = (const float*)d_in[0];
    const float* x_low  = (const float*)d_in[1];
    const float* gamma  = (const float*)d_in[2];
    float* out = (float*)d_out;

    // Phase A: energy = x_low @ x_high^T  (per batch)
    energy_kernel<<<dim3(CH / 128, CH / 128, BATCH), 256>>>(x_high, x_low);

    // Phase B: attention = softmax(-energy) row-wise (in place)
    softmax_kernel<<<(BATCH * CH) / 8, dim3(32, 8)>>>();

    // Phase C: out = gamma * (attention @ x_high) + x_low
    out_kernel<<<dim3(NPIX / 128, CH / 128, BATCH), 256>>>(x_high, x_low, gamma, out);
}

// round 5
// speedup vs baseline: 1.6402x; 1.6402x over previous
#include <cuda_runtime.h>
#include <cuda_fp16.h>
#include <cstdint>

#define BATCH 16
#define CH    512
#define NPIX  4096

// Scratch: energy/attention [B, C, C] = 64 MB (__device__ global, allocation-free)
__device__ float g_energy[(size_t)BATCH * CH * CH];

// ---------------------------------------------------------------------------
// Helpers (family-wide PTX only: cp.async + mma.sync — no tcgen05, harness
// compiles via compute_103 virtual arch which rejects sm_103a-specific ops)
// ---------------------------------------------------------------------------
__device__ __forceinline__ uint32_t smem_u32(const void* p) {
    uint32_t a;
    asm("{ .reg .u64 t; cvta.to.shared.u64 t, %1; cvt.u32.u64 %0, t; }" : "=r"(a) : "l"(p));
    return a;
}
__device__ __forceinline__ void cp16(uint32_t dst, const void* src) {
    asm volatile("cp.async.cg.shared.global [%0], [%1], 16;" :: "r"(dst), "l"(src));
}
__device__ __forceinline__ void cp_commit() { asm volatile("cp.async.commit_group;"); }
template<int N> __device__ __forceinline__ void cp_wait() {
    asm volatile("cp.async.wait_group %0;" :: "n"(N));
}

// double-half split: x = hi + lo, each fp16; packs pairs (x,y) -> h2
__device__ __forceinline__ void split2(float x, float y, uint32_t& hi, uint32_t& lo) {
    __half2 h = __floats2half2_rn(x, y);
    float2 hf = __half22float2(h);
    __half2 l = __floats2half2_rn(x - hf.x, y - hf.y);
    hi = *reinterpret_cast<uint32_t*>(&h);
    lo = *reinterpret_cast<uint32_t*>(&l);
}

__device__ __forceinline__ void mma16816(float* c, const uint32_t* a, const uint32_t* b) {
    asm volatile(
        "mma.sync.aligned.m16n8k16.row.col.f32.f16.f16.f32 "
        "{%0,%1,%2,%3}, {%4,%5,%6,%7}, {%8,%9}, {%0,%1,%2,%3};"
        : "+f"(c[0]), "+f"(c[1]), "+f"(c[2]), "+f"(c[3])
        : "r"(a[0]), "r"(a[1]), "r"(a[2]), "r"(a[3]), "r"(b[0]), "r"(b[1]));
}

// ---------------------------------------------------------------------------
// Kernel 1: energy[b,i,j] = sum_n xl[b,i,n] * xh[b,j,n]
// CTA 128x128, BK=32, 8 warps (2x4), warp 64x32, 4x4 m16n8 tiles, fp16x3 split.
// Smem rows padded to 40 words (conflict-free frag loads).
// ---------------------------------------------------------------------------
#define EAW 40
#define E_TILE_W (128 * EAW)
#define E_SMEM_BYTES (4 * E_TILE_W * 4)   // A[2]+B[2] tiles = 81920 B

__global__ __launch_bounds__(256) void energy_f16(
    const float* __restrict__ xh, const float* __restrict__ xl)
{
    extern __shared__ float sm[];
    float* As = sm;
    float* Bs = sm + 2 * E_TILE_W;
    const int tid  = threadIdx.x;
    const int lane = tid & 31, gid = lane >> 2, tig = lane & 3;
    const int wid  = tid >> 5;
    const int wm = (wid >> 2) * 64, wn = (wid & 3) * 32;
    const int b  = blockIdx.z;
    const int i0 = blockIdx.y * 128, j0 = blockIdx.x * 128;
    const float* Ag = xl + ((size_t)b * CH + i0) * NPIX;
    const float* Bg = xh + ((size_t)b * CH + j0) * NPIX;
    const int lrow = tid >> 1;           // 0..127
    const int lcol = (tid & 1) * 16;     // 0 or 16 (floats)
    const uint32_t sAu = smem_u32(As), sBu = smem_u32(Bs);

    float c[16][4];
    #pragma unroll
    for (int t = 0; t < 16; t++) { c[t][0] = c[t][1] = c[t][2] = c[t][3] = 0.f; }

    {   // prologue: stage 0
        uint32_t da = sAu + (lrow * EAW + lcol) * 4;
        uint32_t db = sBu + (lrow * EAW + lcol) * 4;
        const float* pa = Ag + (size_t)lrow * NPIX + lcol;
        const float* pb = Bg + (size_t)lrow * NPIX + lcol;
        #pragma unroll
        for (int q = 0; q < 4; q++) { cp16(da + q * 16, pa + q * 4); cp16(db + q * 16, pb + q * 4); }
        cp_commit();
    }

    const int NK = NPIX / 32;
    #pragma unroll 1
    for (int it = 0; it < NK; ++it) {
        const int s = it & 1;
        if (it + 1 < NK) {
            const int k0 = (it + 1) * 32;
            uint32_t da = sAu + ((s ^ 1) * E_TILE_W + lrow * EAW + lcol) * 4;
            uint32_t db = sBu + ((s ^ 1) * E_TILE_W + lrow * EAW + lcol) * 4;
            const float* pa = Ag + (size_t)lrow * NPIX + k0 + lcol;
            const float* pb = Bg + (size_t)lrow * NPIX + k0 + lcol;
            #pragma unroll
            for (int q = 0; q < 4; q++) { cp16(da + q * 16, pa + q * 4); cp16(db + q * 16, pb + q * 4); }
            cp_commit();
            cp_wait<1>();
        } else {
            cp_wait<0>();
        }
        __syncthreads();

        const float* A0 = As + s * E_TILE_W;
        const float* B0 = Bs + s * E_TILE_W;
        #pragma unroll
        for (int ks = 0; ks < 2; ks++) {
            const int kb = ks * 16 + 2 * tig;
            uint32_t Bhi[4][2], Blo[4][2];
            #pragma unroll
            for (int nt = 0; nt < 4; nt++) {
                const float* p = B0 + (wn + nt * 8 + gid) * EAW + kb;
                float2 x0 = *(const float2*)p;
                float2 x1 = *(const float2*)(p + 8);
                split2(x0.x, x0.y, Bhi[nt][0], Blo[nt][0]);
                split2(x1.x, x1.y, Bhi[nt][1], Blo[nt][1]);
            }
            #pragma unroll
            for (int mt = 0; mt < 4; mt++) {
                const float* p = A0 + (wm + mt * 16 + gid) * EAW + kb;
                float2 x0 = *(const float2*)p;                 // (gid,   k)
                float2 x1 = *(const float2*)(p + 8 * EAW);     // (gid+8, k)
                float2 x2 = *(const float2*)(p + 8);           // (gid,   k+8)
                float2 x3 = *(const float2*)(p + 8 * EAW + 8); // (gid+8, k+8)
                uint32_t Ahi[4], Alo[4];
                split2(x0.x, x0.y, Ahi[0], Alo[0]);
                split2(x1.x, x1.y, Ahi[1], Alo[1]);
                split2(x2.x, x2.y, Ahi[2], Alo[2]);
                split2(x3.x, x3.y, Ahi[3], Alo[3]);
                #pragma unroll
                for (int nt = 0; nt < 4; nt++) {
                    float* cc = c[mt * 4 + nt];
                    mma16816(cc, Ahi, Bhi[nt]);
                    mma16816(cc, Ahi, Blo[nt]);
                    mma16816(cc, Alo, Bhi[nt]);
                }
            }
        }
        __syncthreads();
    }

    float* E = g_energy + ((size_t)b * CH + i0) * CH + j0;
    #pragma unroll
    for (int mt = 0; mt < 4; mt++) {
        #pragma unroll
        for (int nt = 0; nt < 4; nt++) {
            const float* cc = c[mt * 4 + nt];
            const int r   = wm + mt * 16 + gid;
            const int col = wn + nt * 8 + 2 * tig;
            *(float2*)(E + (size_t)r * CH + col)       = make_float2(cc[0], cc[1]);
            *(float2*)(E + (size_t)(r + 8) * CH + col) = make_float2(cc[2], cc[3]);
        }
    }
}

// ---------------------------------------------------------------------------
// Kernel 2: row softmax of -energy in place: exp(min - e) / sum
// ---------------------------------------------------------------------------
__global__ __launch_bounds__(256) void softmax_kernel()
{
    const int row  = blockIdx.x * 8 + threadIdx.y;
    const int lane = threadIdx.x;
    float* E = g_energy + (size_t)row * CH;

    float4 v[4];
    #pragma unroll
    for (int k = 0; k < 4; k++) v[k] = *(const float4*)(E + lane * 4 + k * 128);

    float mn = v[0].x;
    #pragma unroll
    for (int k = 0; k < 4; k++)
        mn = fminf(mn, fminf(fminf(v[k].x, v[k].y), fminf(v[k].z, v[k].w)));
    #pragma unroll
    for (int off = 16; off > 0; off >>= 1)
        mn = fminf(mn, __shfl_xor_sync(0xFFFFFFFF, mn, off));

    float sum = 0.0f;
    #pragma unroll
    for (int k = 0; k < 4; k++) {
        v[k].x = __expf(mn - v[k].x); v[k].y = __expf(mn - v[k].y);
        v[k].z = __expf(mn - v[k].z); v[k].w = __expf(mn - v[k].w);
        sum += v[k].x + v[k].y + v[k].z + v[k].w;
    }
    #pragma unroll
    for (int off = 16; off > 0; off >>= 1)
        sum += __shfl_xor_sync(0xFFFFFFFF, sum, off);

    const float inv = __frcp_rn(sum);
    #pragma unroll
    for (int k = 0; k < 4; k++) {
        v[k].x *= inv; v[k].y *= inv; v[k].z *= inv; v[k].w *= inv;
        *(float4*)(E + lane * 4 + k * 128) = v[k];
    }
}

// ---------------------------------------------------------------------------
// Kernel 3: out[b,i,n] = gamma * sum_j att[b,i,j] * xh[b,j,n] + xl[b,i,n]
// A = attention (row-major k=j), B = xh ([k=j][n], natural .col layout — no
// transpose). CTA 128x128, BK=32, fp16x3 split, fused epilogue.
// ---------------------------------------------------------------------------
#define CAW 40
#define C_A_TILE_W (128 * CAW)
#define CBW 132
#define C_B_TILE_W (32 * CBW)
#define C_SMEM_BYTES ((2 * C_A_TILE_W + 2 * C_B_TILE_W) * 4)   // 74752 B

__global__ __launch_bounds__(256) void out_f16(
    const float* __restrict__ xh, const float* __restrict__ xl,
    const float* __restrict__ gamma, float* __restrict__ out)
{
    extern __shared__ float sm[];
    float* As = sm;
    float* Bs = sm + 2 * C_A_TILE_W;
    const int tid  = threadIdx.x;
    const int lane = tid & 31, gid = lane >> 2, tig = lane & 3;
    const int wid  = tid >> 5;
    const int wm = (wid >> 2) * 64, wn = (wid & 3) * 32;
    const int b  = blockIdx.z;
    const int i0 = blockIdx.y * 128, n0 = blockIdx.x * 128;
    const float* Ag = g_energy + ((size_t)b * CH + i0) * CH;
    const float* Bg = xh + (size_t)b * CH * NPIX + n0;
    const int larow = tid >> 1, lacol = (tid & 1) * 16;
    const int lbrow = tid >> 3, lbcol = (tid & 7) * 16;
    const uint32_t sAu = smem_u32(As), sBu = smem_u32(Bs);

    float c[16][4];
    #pragma unroll
    for (int t = 0; t < 16; t++) { c[t][0] = c[t][1] = c[t][2] = c[t][3] = 0.f; }

    {   // prologue: stage 0
        uint32_t da = sAu + (larow * CAW + lacol) * 4;
        const float* pa = Ag + (size_t)larow * CH + lacol;
        #pragma unroll
        for (int q = 0; q < 4; q++) cp16(da + q * 16, pa + q * 4);
        uint32_t db = sBu + (lbrow * CBW + lbcol) * 4;
        const float* pb = Bg + (size_t)lbrow * NPIX + lbcol;
        #pragma unroll
        for (int q = 0; q < 4; q++) cp16(db + q * 16, pb + q * 4);
        cp_commit();
    }

    const int NK = CH / 32;
    #pragma unroll 1
    for (int it = 0; it < NK; ++it) {
        const int s = it & 1;
        if (it + 1 < NK) {
            const int k0 = (it + 1) * 32;
            uint32_t da = sAu + ((s ^ 1) * C_A_TILE_W + larow * CAW + lacol) * 4;
            const float* pa = Ag + (size_t)larow * CH + k0 + lacol;
            #pragma unroll
            for (int q = 0; q < 4; q++) cp16(da + q * 16, pa + q * 4);
            uint32_t db = sBu + ((s ^ 1) * C_B_TILE_W + lbrow * CBW + lbcol) * 4;
            const float* pb = Bg + (size_t)(k0 + lbrow) * NPIX + lbcol;
            #pragma unroll
            for (int q = 0; q < 4; q++) cp16(db + q * 16, pb + q * 4);
            cp_commit();
            cp_wait<1>();
        } else {
            cp_wait<0>();
        }
        __syncthreads();

        const float* A0 = As + s * C_A_TILE_W;
        const float* B0 = Bs + s * C_B_TILE_W;
        #pragma unroll
        for (int ks = 0; ks < 2; ks++) {
            const int kb = ks * 16 + 2 * tig;
            uint32_t Bhi[4][2], Blo[4][2];
            #pragma unroll
            for (int nt = 0; nt < 4; nt++) {
                const float* p = B0 + kb * CBW + wn + nt * 8 + gid;
                float x0 = p[0];            // (k,   n)
                float x1 = p[CBW];          // (k+1, n)
                float x2 = p[8 * CBW];      // (k+8, n)
                float x3 = p[9 * CBW];      // (k+9, n)
                split2(x0, x1, Bhi[nt][0], Blo[nt][0]);
                split2(x2, x3, Bhi[nt][1], Blo[nt][1]);
            }
            #pragma unroll
            for (int mt = 0; mt < 4; mt++) {
                const float* p = A0 + (wm + mt * 16 + gid) * CAW + kb;
                float2 x0 = *(const float2*)p;
                float2 x1 = *(const float2*)(p + 8 * CAW);
                float2 x2 = *(const float2*)(p + 8);
                float2 x3 = *(const float2*)(p + 8 * CAW + 8);
                uint32_t Ahi[4], Alo[4];
                split2(x0.x, x0.y, Ahi[0], Alo[0]);
                split2(x1.x, x1.y, Ahi[1], Alo[1]);
                split2(x2.x, x2.y, Ahi[2], Alo[2]);
                split2(x3.x, x3.y, Ahi[3], Alo[3]);
                #pragma unroll
                for (int nt = 0; nt < 4; nt++) {
                    float* cc = c[mt * 4 + nt];
                    mma16816(cc, Ahi, Bhi[nt]);
                    mma16816(cc, Ahi, Blo[nt]);
                    mma16816(cc, Alo, Bhi[nt]);
                }
            }
        }
        __syncthreads();
    }

    const float g = gamma[0];
    #pragma unroll
    for (int mt = 0; mt < 4; mt++) {
        #pragma unroll
        for (int nt = 0; nt < 4; nt++) {
            const float* cc = c[mt * 4 + nt];
            const int r   = i0 + wm + mt * 16 + gid;
            const int col = n0 + wn + nt * 8 + 2 * tig;
            size_t off0 = ((size_t)b * CH + r) * NPIX + col;
            size_t off1 = ((size_t)b * CH + r + 8) * NPIX + col;
            float2 l0 = *(const float2*)(xl + off0);
            float2 l1 = *(const float2*)(xl + off1);
            *(float2*)(out + off0) = make_float2(fmaf(g, cc[0], l0.x), fmaf(g, cc[1], l0.y));
            *(float2*)(out + off1) = make_float2(fmaf(g, cc[2], l1.x), fmaf(g, cc[3], l1.y));
        }
    }
}

// ---------------------------------------------------------------------------
extern "C" void kernel_launch(void* const* d_in, const int* in_sizes, int n_in,
                              void* d_out, int out_size)
{
    const float* x_high = (const float*)d_in[0];
    const float* x_low  = (const float*)d_in[1];
    const float* gamma  = (const float*)d_in[2];
    float* out = (float*)d_out;

    cudaFuncSetAttribute(energy_f16, cudaFuncAttributeMaxDynamicSharedMemorySize, E_SMEM_BYTES);
    cudaFuncSetAttribute(out_f16,    cudaFuncAttributeMaxDynamicSharedMemorySize, C_SMEM_BYTES);

    energy_f16<<<dim3(CH / 128, CH / 128, BATCH), 256, E_SMEM_BYTES>>>(x_high, x_low);
    softmax_kernel<<<(BATCH * CH) / 8, dim3(32, 8)>>>();
    out_f16<<<dim3(NPIX / 128, CH / 128, BATCH), 256, C_SMEM_BYTES>>>(x_high, x_low, gamma, out);
}

// round 8
// speedup vs baseline: 2.1947x; 1.3381x over previous
#include <cuda_runtime.h>
#include <cuda_fp16.h>
#include <cstdint>

#define BATCH 16
#define CH    512
#define NPIX  4096

// Scratch (__device__ globals — allocation-free per harness rules)
__device__ float  g_energy[(size_t)BATCH * CH * CH];      // 64 MB
__device__ __half g_xh_hi[(size_t)BATCH * CH * NPIX];     // 64 MB
__device__ __half g_xh_lo[(size_t)BATCH * CH * NPIX];     // 64 MB
__device__ __half g_xl_hi[(size_t)BATCH * CH * NPIX];     // 64 MB
__device__ __half g_xl_lo[(size_t)BATCH * CH * NPIX];     // 64 MB
__device__ __half g_att_hi[(size_t)BATCH * CH * CH];      // 16 MB
__device__ __half g_att_lo[(size_t)BATCH * CH * CH];      // 16 MB

// ---------------------------------------------------------------------------
// PTX helpers (family-wide: cp.async, ldmatrix, mma.sync — compute_103-safe)
// ---------------------------------------------------------------------------
__device__ __forceinline__ uint32_t smem_u32(const void* p) {
    uint32_t a;
    asm("{ .reg .u64 t; cvta.to.shared.u64 t, %1; cvt.u32.u64 %0, t; }" : "=r"(a) : "l"(p));
    return a;
}
__device__ __forceinline__ void cp16(uint32_t dst, const void* src) {
    asm volatile("cp.async.cg.shared.global [%0], [%1], 16;" :: "r"(dst), "l"(src));
}
__device__ __forceinline__ void cp_commit() { asm volatile("cp.async.commit_group;"); }
template<int N> __device__ __forceinline__ void cp_wait() {
    asm volatile("cp.async.wait_group %0;" :: "n"(N));
}
__device__ __forceinline__ void ldsm4(uint32_t* r, uint32_t a) {
    asm volatile("ldmatrix.sync.aligned.m8n8.x4.shared.b16 {%0,%1,%2,%3}, [%4];"
                 : "=r"(r[0]), "=r"(r[1]), "=r"(r[2]), "=r"(r[3]) : "r"(a));
}
__device__ __forceinline__ void ldsm4t(uint32_t* r, uint32_t a) {
    asm volatile("ldmatrix.sync.aligned.m8n8.x4.trans.shared.b16 {%0,%1,%2,%3}, [%4];"
                 : "=r"(r[0]), "=r"(r[1]), "=r"(r[2]), "=r"(r[3]) : "r"(a));
}
__device__ __forceinline__ void mma16816(float* c, const uint32_t* a, const uint32_t* b) {
    asm volatile(
        "mma.sync.aligned.m16n8k16.row.col.f32.f16.f16.f32 "
        "{%0,%1,%2,%3}, {%4,%5,%6,%7}, {%8,%9}, {%0,%1,%2,%3};"
        : "+f"(c[0]), "+f"(c[1]), "+f"(c[2]), "+f"(c[3])
        : "r"(a[0]), "r"(a[1]), "r"(a[2]), "r"(a[3]), "r"(b[0]), "r"(b[1]));
}

// ---------------------------------------------------------------------------
// Kernel 0: split x_high, x_low into fp16 (hi, lo) pairs. x = hi + lo exactly
// to ~2^-22. Pure streaming: 256MB read + 256MB write.
// Each thread handles 8 floats.
// ---------------------------------------------------------------------------
__global__ __launch_bounds__(256) void split_kernel(
    const float* __restrict__ xh, const float* __restrict__ xl)
{
    const size_t n8 = (size_t)BATCH * CH * NPIX / 8;
    size_t i = (size_t)blockIdx.x * blockDim.x + threadIdx.x;
    const float* src; __half *hi, *lo;
    if (i < n8) { src = xh; hi = g_xh_hi; lo = g_xh_lo; }
    else        { i -= n8; src = xl; hi = g_xl_hi; lo = g_xl_lo; }

    float4 v0 = *(const float4*)(src + i * 8);
    float4 v1 = *(const float4*)(src + i * 8 + 4);
    __half2 h0 = __floats2half2_rn(v0.x, v0.y);
    __half2 h1 = __floats2half2_rn(v0.z, v0.w);
    __half2 h2 = __floats2half2_rn(v1.x, v1.y);
    __half2 h3 = __floats2half2_rn(v1.z, v1.w);
    float2 f0 = __half22float2(h0), f1 = __half22float2(h1);
    float2 f2 = __half22float2(h2), f3 = __half22float2(h3);
    __half2 l0 = __floats2half2_rn(v0.x - f0.x, v0.y - f0.y);
    __half2 l1 = __floats2half2_rn(v0.z - f1.x, v0.w - f1.y);
    __half2 l2 = __floats2half2_rn(v1.x - f2.x, v1.y - f2.y);
    __half2 l3 = __floats2half2_rn(v1.z - f3.x, v1.w - f3.y);
    uint4 hv, lv;
    hv.x = *(uint32_t*)&h0; hv.y = *(uint32_t*)&h1; hv.z = *(uint32_t*)&h2; hv.w = *(uint32_t*)&h3;
    lv.x = *(uint32_t*)&l0; lv.y = *(uint32_t*)&l1; lv.z = *(uint32_t*)&l2; lv.w = *(uint32_t*)&l3;
    *(uint4*)(hi + i * 8) = hv;
    *(uint4*)(lo + i * 8) = lv;
}

// ---------------------------------------------------------------------------
// Kernel 1: energy[b,i,j] = sum_n xl[b,i,n] * xh[b,j,n]   (fp16x3, hoisted splits)
// CTA 128x128, BK=32, 8 warps (2x4), warp 64x32. Pure LDSM+HMMA mainloop.
// Smem per stage: Ah,Al,Bh,Bl each 128 rows x 40 halfs (80B rows, conflict-free).
// ---------------------------------------------------------------------------
#define EROWB   80                    // bytes per smem row (32 halfs + 8 pad)
#define EMATB   (128 * EROWB)         // 10240 B per matrix
#define ESTGB   (4 * EMATB)           // 40960 B per stage
#define E_SMEM  (2 * ESTGB)           // 81920 B

__global__ __launch_bounds__(256, 2) void energy_f16(
    const float* __restrict__ xh_unused, const float* __restrict__ xl_unused)
{
    extern __shared__ char smc[];
    const uint32_t sbu = smem_u32(smc);
    const int tid  = threadIdx.x;
    const int lane = tid & 31;
    const int wid  = tid >> 5;
    const int wm = (wid >> 2) * 64, wn = (wid & 3) * 32;
    const int b  = blockIdx.z;
    const int i0 = blockIdx.y * 128, j0 = blockIdx.x * 128;

    const __half* Ahg = g_xl_hi + ((size_t)b * CH + i0) * NPIX;
    const __half* Alg = g_xl_lo + ((size_t)b * CH + i0) * NPIX;
    const __half* Bhg = g_xh_hi + ((size_t)b * CH + j0) * NPIX;
    const __half* Blg = g_xh_lo + ((size_t)b * CH + j0) * NPIX;

    // loaders: thread -> row (0..127), chunk pair (2 x 16B)
    const int lrow = tid >> 1;
    const int lcq  = (tid & 1) * 2;            // chunk 0..3 (16B = 8 halfs each)

    // ldmatrix lane addressing (bytes, within a matrix)
    const int a_r = (lane & 7) + ((lane >> 3) & 1) * 8;       // row 0..15
    const int a_c = (lane >> 4) & 1;                          // k-chunk
    const uint32_t aoff = (uint32_t)(wm + a_r) * EROWB + a_c * 16;
    const int b_r = (lane & 7) + ((lane >> 4) & 1) * 8;       // n-row within pair
    const int b_c = (lane >> 3) & 1;                          // k-chunk
    const uint32_t boff = (uint32_t)(wn + b_r) * EROWB + b_c * 16;

    float c[16][4];
    #pragma unroll
    for (int t = 0; t < 16; t++) { c[t][0] = c[t][1] = c[t][2] = c[t][3] = 0.f; }

    {   // prologue: stage 0 (k0 = 0)
        const uint32_t d0 = sbu + (uint32_t)lrow * EROWB + lcq * 16;
        const size_t so = (size_t)lrow * NPIX + lcq * 8;
        #pragma unroll
        for (int q = 0; q < 2; q++) {
            cp16(d0 + q * 16,             Ahg + so + q * 8);
            cp16(d0 + q * 16 + EMATB,     Alg + so + q * 8);
            cp16(d0 + q * 16 + 2 * EMATB, Bhg + so + q * 8);
            cp16(d0 + q * 16 + 3 * EMATB, Blg + so + q * 8);
        }
        cp_commit();
    }

    const int NK = NPIX / 32;
    #pragma unroll 1
    for (int it = 0; it < NK; ++it) {
        const int s = it & 1;
        if (it + 1 < NK) {
            const int k0 = (it + 1) * 32;
            const uint32_t d0 = sbu + (s ^ 1) * ESTGB + (uint32_t)lrow * EROWB + lcq * 16;
            const size_t so = (size_t)lrow * NPIX + k0 + lcq * 8;
            #pragma unroll
            for (int q = 0; q < 2; q++) {
                cp16(d0 + q * 16,             Ahg + so + q * 8);
                cp16(d0 + q * 16 + EMATB,     Alg + so + q * 8);
                cp16(d0 + q * 16 + 2 * EMATB, Bhg + so + q * 8);
                cp16(d0 + q * 16 + 3 * EMATB, Blg + so + q * 8);
            }
            cp_commit();
            cp_wait<1>();
        } else {
            cp_wait<0>();
        }
        __syncthreads();

        const uint32_t sg = sbu + s * ESTGB;
        #pragma unroll
        for (int ks = 0; ks < 2; ks++) {
            uint32_t Bh[8], Bl[8];
            ldsm4(Bh + 0, sg + 2 * EMATB + boff + ks * 32);
            ldsm4(Bh + 4, sg + 2 * EMATB + boff + ks * 32 + 16 * EROWB);
            ldsm4(Bl + 0, sg + 3 * EMATB + boff + ks * 32);
            ldsm4(Bl + 4, sg + 3 * EMATB + boff + ks * 32 + 16 * EROWB);
            #pragma unroll
            for (int mt = 0; mt < 4; mt++) {
                uint32_t Ah[4], Al[4];
                ldsm4(Ah, sg + aoff + mt * 16 * EROWB + ks * 32);
                ldsm4(Al, sg + EMATB + aoff + mt * 16 * EROWB + ks * 32);
                #pragma unroll
                for (int nt = 0; nt < 4; nt++) {
                    float* cc = c[mt * 4 + nt];
                    mma16816(cc, Ah, Bh + nt * 2);
                    mma16816(cc, Ah, Bl + nt * 2);
                    mma16816(cc, Al, Bh + nt * 2);
                }
            }
        }
        __syncthreads();
    }

    const int gid = lane >> 2, tig = lane & 3;
    float* E = g_energy + ((size_t)b * CH + i0) * CH + j0;
    #pragma unroll
    for (int mt = 0; mt < 4; mt++) {
        #pragma unroll
        for (int nt = 0; nt < 4; nt++) {
            const float* cc = c[mt * 4 + nt];
            const int r   = wm + mt * 16 + gid;
            const int col = wn + nt * 8 + 2 * tig;
            *(float2*)(E + (size_t)r * CH + col)       = make_float2(cc[0], cc[1]);
            *(float2*)(E + (size_t)(r + 8) * CH + col) = make_float2(cc[2], cc[3]);
        }
    }
}

// ---------------------------------------------------------------------------
// Kernel 2: row softmax of -energy -> attention hi/lo halves.
// att = exp(min - e) / sum. Writes fp16 hi + lo (hi+lo ~ fp32 to 2^-22).
// ---------------------------------------------------------------------------
__global__ __launch_bounds__(256) void softmax_kernel()
{
    const int row  = blockIdx.x * 8 + threadIdx.y;
    const int lane = threadIdx.x;
    const float* E = g_energy + (size_t)row * CH;

    float4 v[4];
    #pragma unroll
    for (int k = 0; k < 4; k++) v[k] = *(const float4*)(E + lane * 4 + k * 128);

    float mn = v[0].x;
    #pragma unroll
    for (int k = 0; k < 4; k++)
        mn = fminf(mn, fminf(fminf(v[k].x, v[k].y), fminf(v[k].z, v[k].w)));
    #pragma unroll
    for (int off = 16; off > 0; off >>= 1)
        mn = fminf(mn, __shfl_xor_sync(0xFFFFFFFF, mn, off));

    float sum = 0.0f;
    #pragma unroll
    for (int k = 0; k < 4; k++) {
        v[k].x = __expf(mn - v[k].x); v[k].y = __expf(mn - v[k].y);
        v[k].z = __expf(mn - v[k].z); v[k].w = __expf(mn - v[k].w);
        sum += v[k].x + v[k].y + v[k].z + v[k].w;
    }
    #pragma unroll
    for (int off = 16; off > 0; off >>= 1)
        sum += __shfl_xor_sync(0xFFFFFFFF, sum, off);

    const float inv = __frcp_rn(sum);
    __half* AH = g_att_hi + (size_t)row * CH;
    __half* AL = g_att_lo + (size_t)row * CH;
    #pragma unroll
    for (int k = 0; k < 4; k++) {
        float a0 = v[k].x * inv, a1 = v[k].y * inv, a2 = v[k].z * inv, a3 = v[k].w * inv;
        __half2 h0 = __floats2half2_rn(a0, a1);
        __half2 h1 = __floats2half2_rn(a2, a3);
        float2 f0 = __half22float2(h0), f1 = __half22float2(h1);
        __half2 l0 = __floats2half2_rn(a0 - f0.x, a1 - f0.y);
        __half2 l1 = __floats2half2_rn(a2 - f1.x, a3 - f1.y);
        uint2 hv, lv;
        hv.x = *(uint32_t*)&h0; hv.y = *(uint32_t*)&h1;
        lv.x = *(uint32_t*)&l0; lv.y = *(uint32_t*)&l1;
        *(uint2*)(AH + lane * 4 + k * 128) = hv;
        *(uint2*)(AL + lane * 4 + k * 128) = lv;
    }
}

// ---------------------------------------------------------------------------
// Kernel 3: out[b,i,n] = gamma * sum_j att[b,i,j]*xh[b,j,n] + xl[b,i,n]
// A = attention hi/lo (i rows, j=k contiguous). B = xh hi/lo ([j=k][n],
// loaded via ldmatrix.trans). CTA 128x128, BK=32, fp16x3, fused epilogue.
// ---------------------------------------------------------------------------
#define OAROWB  80                     // A: 32 halfs + pad -> 80 B rows
#define OAMATB  (128 * OAROWB)         // 10240 B
#define OBROWB  272                    // B: 128 halfs + pad -> 272 B rows
#define OBMATB  (32 * OBROWB)          // 8704 B
#define OSTGB   (2 * OAMATB + 2 * OBMATB)   // 37888 B
#define O_SMEM  (2 * OSTGB)            // 75776 B

__global__ __launch_bounds__(256, 2) void out_f16(
    const float* __restrict__ xl, const float* __restrict__ gamma,
    float* __restrict__ out)
{
    extern __shared__ char smc[];
    const uint32_t sbu = smem_u32(smc);
    const int tid  = threadIdx.x;
    const int lane = tid & 31;
    const int wid  = tid >> 5;
    const int wm = (wid >> 2) * 64, wn = (wid & 3) * 32;
    const int b  = blockIdx.z;
    const int i0 = blockIdx.y * 128, n0 = blockIdx.x * 128;

    const __half* Ahg = g_att_hi + ((size_t)b * CH + i0) * CH;
    const __half* Alg = g_att_lo + ((size_t)b * CH + i0) * CH;
    const __half* Bhg = g_xh_hi + (size_t)b * CH * NPIX + n0;
    const __half* Blg = g_xh_lo + (size_t)b * CH * NPIX + n0;

    // A loader: row 0..127, 2 chunks of 16B (32 halfs per row)
    const int larow = tid >> 1, lacq = (tid & 1) * 2;
    // B loader: row 0..31 (k), 2 of 16 chunks (128 halfs per row)
    const int lbrow = tid >> 3, lbcq = (tid & 7) * 2;

    // ldmatrix lane addressing
    const int a_r = (lane & 7) + ((lane >> 3) & 1) * 8;
    const int a_c = (lane >> 4) & 1;
    const uint32_t aoff = (uint32_t)(wm + a_r) * OAROWB + a_c * 16;
    // B (trans): stored row = k, col chunk = n
    const int t_k = (lane & 7) + ((lane >> 3) & 1) * 8;       // k row 0..15
    const int t_n = ((lane >> 4) & 1) * 8;                    // n within pair
    const uint32_t boff = (uint32_t)t_k * OBROWB + (uint32_t)(wn + t_n) * 2;

    float c[16][4];
    #pragma unroll
    for (int t = 0; t < 16; t++) { c[t][0] = c[t][1] = c[t][2] = c[t][3] = 0.f; }

    {   // prologue stage 0
        const uint32_t da = sbu + (uint32_t)larow * OAROWB + lacq * 16;
        const size_t sa = (size_t)larow * CH + lacq * 8;
        const uint32_t db = sbu + 2 * OAMATB + (uint32_t)lbrow * OBROWB + lbcq * 16;
        const size_t sbg = (size_t)lbrow * NPIX + lbcq * 8;
        #pragma unroll
        for (int q = 0; q < 2; q++) {
            cp16(da + q * 16,           Ahg + sa + q * 8);
            cp16(da + q * 16 + OAMATB,  Alg + sa + q * 8);
            cp16(db + q * 16,           Bhg + sbg + q * 8);
            cp16(db + q * 16 + OBMATB,  Blg + sbg + q * 8);
        }
        cp_commit();
    }

    const int NK = CH / 32;
    #pragma unroll 1
    for (int it = 0; it < NK; ++it) {
        const int s = it & 1;
        if (it + 1 < NK) {
            const int k0 = (it + 1) * 32;
            const uint32_t da = sbu + (s ^ 1) * OSTGB + (uint32_t)larow * OAROWB + lacq * 16;
            const size_t sa = (size_t)larow * CH + k0 + lacq * 8;
            const uint32_t db = sbu + (s ^ 1) * OSTGB + 2 * OAMATB + (uint32_t)lbrow * OBROWB + lbcq * 16;
            const size_t sbg = (size_t)(k0 + lbrow) * NPIX + lbcq * 8;
            #pragma unroll
            for (int q = 0; q < 2; q++) {
                cp16(da + q * 16,           Ahg + sa + q * 8);
                cp16(da + q * 16 + OAMATB,  Alg + sa + q * 8);
                cp16(db + q * 16,           Bhg + sbg + q * 8);
                cp16(db + q * 16 + OBMATB,  Blg + sbg + q * 8);
            }
            cp_commit();
            cp_wait<1>();
        } else {
            cp_wait<0>();
        }
        __syncthreads();

        const uint32_t sg = sbu + s * OSTGB;
        #pragma unroll
        for (int ks = 0; ks < 2; ks++) {
            uint32_t Bh[8], Bl[8];
            ldsm4t(Bh + 0, sg + 2 * OAMATB + boff + ks * 16 * OBROWB);
            ldsm4t(Bh + 4, sg + 2 * OAMATB + boff + ks * 16 * OBROWB + 32);
            ldsm4t(Bl + 0, sg + 2 * OAMATB + OBMATB + boff + ks * 16 * OBROWB);
            ldsm4t(Bl + 4, sg + 2 * OAMATB + OBMATB + boff + ks * 16 * OBROWB + 32);
            #pragma unroll
            for (int mt = 0; mt < 4; mt++) {
                uint32_t Ah[4], Al[4];
                ldsm4(Ah, sg + aoff + mt * 16 * OAROWB + ks * 32);
                ldsm4(Al, sg + OAMATB + aoff + mt * 16 * OAROWB + ks * 32);
                #pragma unroll
                for (int nt = 0; nt < 4; nt++) {
                    float* cc = c[mt * 4 + nt];
                    mma16816(cc, Ah, Bh + nt * 2);
                    mma16816(cc, Ah, Bl + nt * 2);
                    mma16816(cc, Al, Bh + nt * 2);
                }
            }
        }
        __syncthreads();
    }

    const int gid = lane >> 2, tig = lane & 3;
    const float g = gamma[0];
    #pragma unroll
    for (int mt = 0; mt < 4; mt++) {
        #pragma unroll
        for (int nt = 0; nt < 4; nt++) {
            const float* cc = c[mt * 4 + nt];
            const int r   = i0 + wm + mt * 16 + gid;
            const int col = n0 + wn + nt * 8 + 2 * tig;
            size_t off0 = ((size_t)b * CH + r) * NPIX + col;
            size_t off1 = ((size_t)b * CH + r + 8) * NPIX + col;
            float2 l0 = *(const float2*)(xl + off0);
            float2 l1 = *(const float2*)(xl + off1);
            *(float2*)(out + off0) = make_float2(fmaf(g, cc[0], l0.x), fmaf(g, cc[1], l0.y));
            *(float2*)(out + off1) = make_float2(fmaf(g, cc[2], l1.x), fmaf(g, cc[3], l1.y));
        }
    }
}

// ---------------------------------------------------------------------------
extern "C" void kernel_launch(void* const* d_in, const int* in_sizes, int n_in,
                              void* d_out, int out_size)
{
    const float* x_high = (const float*)d_in[0];
    const float* x_low  = (const float*)d_in[1];
    const float* gamma  = (const float*)d_in[2];
    float* out = (float*)d_out;

    cudaFuncSetAttribute(energy_f16, cudaFuncAttributeMaxDynamicSharedMemorySize, E_SMEM);
    cudaFuncSetAttribute(out_f16,    cudaFuncAttributeMaxDynamicSharedMemorySize, O_SMEM);

    const size_t n8 = (size_t)BATCH * CH * NPIX / 8;          // per-tensor vec8 count
    split_kernel<<<(unsigned)(2 * n8 / 256), 256>>>(x_high, x_low);
    energy_f16<<<dim3(CH / 128, CH / 128, BATCH), 256, E_SMEM>>>(x_high, x_low);
    softmax_kernel<<<(BATCH * CH) / 8, dim3(32, 8)>>>();
    out_f16<<<dim3(NPIX / 128, CH / 128, BATCH), 256, O_SMEM>>>(x_low, gamma, out);
}